// round 4
// baseline (speedup 1.0000x reference)
#include <cuda_runtime.h>

#define MAX_N 100000
#define MAX_E 1000000
#define D 64

// Scratch (device globals: sanctioned alternative to cudaMalloc)
__device__ float g_h[MAX_N * D];     // h = x @ W^T
__device__ float g_dinv[MAX_N];
__device__ int   g_cnt[MAX_N];       // in-degree (excl. self-loop)
__device__ int   g_start[MAX_N];     // CSR row starts (exclusive scan of cnt)
__device__ int   g_cursor[MAX_N];    // fill cursors
__device__ int   g_ebuf[MAX_E];      // src node per edge, bucketed by dst
__device__ int   g_bsum[128];        // scan block sums

// ---------------------------------------------------------------------------
// 1) zero the degree histogram
// ---------------------------------------------------------------------------
__global__ void zero_cnt_kernel(int N) {
    int i = blockIdx.x * blockDim.x + threadIdx.x;
    if (i < N) g_cnt[i] = 0;
}

// 2) histogram in-degree over edge dst (edge_index is int32)
__global__ void deg_acc_kernel(const int* __restrict__ ei, int E) {
    int e = blockIdx.x * blockDim.x + threadIdx.x;
    if (e < E) atomicAdd(&g_cnt[ei[E + e]], 1);
}

// ---------------------------------------------------------------------------
// 3) two-level exclusive scan of g_cnt -> g_start
// ---------------------------------------------------------------------------
__global__ __launch_bounds__(1024)
void scan1_kernel(int N) {
    __shared__ int wsum[32];
    int i = blockIdx.x * 1024 + threadIdx.x;
    int lane = threadIdx.x & 31;
    int wid  = threadIdx.x >> 5;
    int v = (i < N) ? g_cnt[i] : 0;
    int val = v;
#pragma unroll
    for (int off = 1; off < 32; off <<= 1) {
        int t = __shfl_up_sync(0xffffffffu, val, off);
        if (lane >= off) val += t;
    }
    if (lane == 31) wsum[wid] = val;
    __syncthreads();
    if (wid == 0) {
        int w = wsum[lane];
#pragma unroll
        for (int off = 1; off < 32; off <<= 1) {
            int t = __shfl_up_sync(0xffffffffu, w, off);
            if (lane >= off) w += t;
        }
        wsum[lane] = w;
    }
    __syncthreads();
    int incl = val + (wid > 0 ? wsum[wid - 1] : 0);
    if (i < N) g_start[i] = incl - v;
    if (threadIdx.x == 1023) g_bsum[blockIdx.x] = incl;
}

__global__ __launch_bounds__(128)
void scan2_kernel(int nb) {
    __shared__ int wsum[4];
    int lane = threadIdx.x & 31;
    int wid  = threadIdx.x >> 5;
    int v = (threadIdx.x < nb) ? g_bsum[threadIdx.x] : 0;
    int val = v;
#pragma unroll
    for (int off = 1; off < 32; off <<= 1) {
        int t = __shfl_up_sync(0xffffffffu, val, off);
        if (lane >= off) val += t;
    }
    if (lane == 31) wsum[wid] = val;
    __syncthreads();
    int pre = 0;
    for (int w = 0; w < wid; w++) pre += wsum[w];
    if (threadIdx.x < nb) g_bsum[threadIdx.x] = val - v + pre;  // exclusive
}

__global__ void scan3_kernel(int N) {
    int i = blockIdx.x * blockDim.x + threadIdx.x;
    if (i < N) {
        int s = g_start[i] + g_bsum[i >> 10];
        g_start[i]  = s;
        g_cursor[i] = s;
    }
}

// 4) bucket fill: edges grouped by dst, payload = src
__global__ void fill_kernel(const int* __restrict__ ei, int E) {
    int e = blockIdx.x * blockDim.x + threadIdx.x;
    if (e < E) {
        int s = ei[e];
        int d = ei[E + e];
        int pos = atomicAdd(&g_cursor[d], 1);
        g_ebuf[pos] = s;
    }
}

// ---------------------------------------------------------------------------
// 5) GEMM: h[n][o] = sum_k x[n][k] * W[o][k]
//    4 threads per node, 16 outputs each (f32x2 accumulators, ~40 regs
//    -> high occupancy). Also computes dinv[n] = rsqrt(1 + indeg).
// ---------------------------------------------------------------------------
__global__ __launch_bounds__(256)
void gemm_kernel(const float* __restrict__ x,
                 const float* __restrict__ W,
                 int N) {
    __shared__ float Ws[D * D];   // Ws[k*64 + o] = W[o][k]  (transposed)
    for (int t = threadIdx.x; t < D * D; t += 256) {
        int o = t >> 6;
        int k = t & 63;
        Ws[k * D + o] = W[t];
    }
    __syncthreads();

    int t = blockIdx.x * 256 + threadIdx.x;
    if (t >= N * 4) return;
    int n = t >> 2;
    int q = t & 3;                 // output quarter: cols [16q, 16q+16)

    unsigned long long acc[8];
#pragma unroll
    for (int m = 0; m < 8; m++) acc[m] = 0ULL;

    const float4* xr = (const float4*)(x + (size_t)n * D);

#pragma unroll 1
    for (int i4 = 0; i4 < 16; i4++) {
        float4 xv = xr[i4];
        float xs[4] = {xv.x, xv.y, xv.z, xv.w};
#pragma unroll
        for (int kk = 0; kk < 4; kk++) {
            int k = i4 * 4 + kk;
            unsigned long long xx;
            asm("mov.b64 %0, {%1, %1};" : "=l"(xx) : "f"(xs[kk]));
            const ulonglong2* wp = (const ulonglong2*)(Ws + k * D + q * 16);
            ulonglong2 w0 = wp[0], w1 = wp[1], w2 = wp[2], w3 = wp[3];
            asm("fma.rn.f32x2 %0, %1, %2, %0;" : "+l"(acc[0]) : "l"(xx), "l"(w0.x));
            asm("fma.rn.f32x2 %0, %1, %2, %0;" : "+l"(acc[1]) : "l"(xx), "l"(w0.y));
            asm("fma.rn.f32x2 %0, %1, %2, %0;" : "+l"(acc[2]) : "l"(xx), "l"(w1.x));
            asm("fma.rn.f32x2 %0, %1, %2, %0;" : "+l"(acc[3]) : "l"(xx), "l"(w1.y));
            asm("fma.rn.f32x2 %0, %1, %2, %0;" : "+l"(acc[4]) : "l"(xx), "l"(w2.x));
            asm("fma.rn.f32x2 %0, %1, %2, %0;" : "+l"(acc[5]) : "l"(xx), "l"(w2.y));
            asm("fma.rn.f32x2 %0, %1, %2, %0;" : "+l"(acc[6]) : "l"(xx), "l"(w3.x));
            asm("fma.rn.f32x2 %0, %1, %2, %0;" : "+l"(acc[7]) : "l"(xx), "l"(w3.y));
        }
    }

    if (q == 0) g_dinv[n] = rsqrtf(1.0f + (float)g_cnt[n]);

    float* hrow = g_h + (size_t)n * D + q * 16;
#pragma unroll
    for (int m = 0; m < 4; m++) {
        float f0, f1, f2, f3;
        asm("mov.b64 {%0, %1}, %2;" : "=f"(f0), "=f"(f1) : "l"(acc[2 * m]));
        asm("mov.b64 {%0, %1}, %2;" : "=f"(f2), "=f"(f3) : "l"(acc[2 * m + 1]));
        ((float4*)hrow)[m] = make_float4(f0, f1, f2, f3);
    }
}

// ---------------------------------------------------------------------------
// 6) Gather: one warp per node.
//    out[n] = b + dinv[n]^2 * h[n] + dinv[n] * sum_{s in in(n)} dinv[s]*h[s]
//    No atomics; out written exactly once (covers the poisoned buffer).
// ---------------------------------------------------------------------------
__global__ __launch_bounds__(256)
void gather_kernel(const float* __restrict__ bias,
                   float* __restrict__ out, int N) {
    int warp = (blockIdx.x * 256 + threadIdx.x) >> 5;
    int lane = threadIdx.x & 31;
    if (warp >= N) return;
    int n = warp;

    int start = g_start[n];
    int cnt   = g_cnt[n];

    float2 acc0 = make_float2(0.f, 0.f);
    float2 acc1 = make_float2(0.f, 0.f);

    int i = 0;
    for (; i + 2 <= cnt; i += 2) {
        int s0 = __ldg(&g_ebuf[start + i]);
        int s1 = __ldg(&g_ebuf[start + i + 1]);
        float d0 = g_dinv[s0];
        float d1 = g_dinv[s1];
        float2 v0 = ((const float2*)g_h)[(size_t)s0 * 32 + lane];
        float2 v1 = ((const float2*)g_h)[(size_t)s1 * 32 + lane];
        acc0.x = fmaf(d0, v0.x, acc0.x);
        acc0.y = fmaf(d0, v0.y, acc0.y);
        acc1.x = fmaf(d1, v1.x, acc1.x);
        acc1.y = fmaf(d1, v1.y, acc1.y);
    }
    if (i < cnt) {
        int s0 = __ldg(&g_ebuf[start + i]);
        float d0 = g_dinv[s0];
        float2 v0 = ((const float2*)g_h)[(size_t)s0 * 32 + lane];
        acc0.x = fmaf(d0, v0.x, acc0.x);
        acc0.y = fmaf(d0, v0.y, acc0.y);
    }
    acc0.x += acc1.x;
    acc0.y += acc1.y;

    float dn  = g_dinv[n];
    float sl  = dn * dn;
    float2 hn = ((const float2*)g_h)[(size_t)n * 32 + lane];
    float2 bb = ((const float2*)bias)[lane];
    float2 o;
    o.x = bb.x + sl * hn.x + dn * acc0.x;
    o.y = bb.y + sl * hn.y + dn * acc0.y;
    ((float2*)out)[(size_t)n * 32 + lane] = o;
}

// ---------------------------------------------------------------------------
extern "C" void kernel_launch(void* const* d_in, const int* in_sizes, int n_in,
                              void* d_out, int out_size) {
    const float* x  = (const float*)d_in[0];
    const int*   ei = (const int*)d_in[1];
    const float* W  = (const float*)d_in[2];
    const float* b  = (const float*)d_in[3];
    float*       out = (float*)d_out;

    int N = in_sizes[0] / D;   // 100000
    int E = in_sizes[1] / 2;   // 1000000
    int nb = (N + 1023) / 1024;

    zero_cnt_kernel<<<(N + 255) / 256, 256>>>(N);
    deg_acc_kernel<<<(E + 255) / 256, 256>>>(ei, E);
    scan1_kernel<<<nb, 1024>>>(N);
    scan2_kernel<<<1, 128>>>(nb);
    scan3_kernel<<<(N + 255) / 256, 256>>>(N);
    fill_kernel<<<(E + 255) / 256, 256>>>(ei, E);
    gemm_kernel<<<(N * 4 + 255) / 256, 256>>>(x, W, N);
    gather_kernel<<<(N * 32 + 255) / 256, 256>>>(b, out, N);
}

// round 5
// speedup vs baseline: 1.0050x; 1.0050x over previous
#include <cuda_runtime.h>

#define MAX_N 100000
#define D 64

// Scratch (device globals: sanctioned alternative to cudaMalloc)
__device__ float g_h[MAX_N * D];     // h = x @ W^T
__device__ float g_deg[MAX_N];
__device__ float g_dinv[MAX_N];

// ---------------------------------------------------------------------------
// 1) degree init: every node gets a self-loop -> deg starts at 1
// ---------------------------------------------------------------------------
__global__ void deg_init_kernel(int N4) {
    int i = blockIdx.x * blockDim.x + threadIdx.x;
    if (i < N4) ((float4*)g_deg)[i] = make_float4(1.f, 1.f, 1.f, 1.f);
}

// 2) accumulate in-degree over edge dst (edge_index is int32)
__global__ void deg_acc_kernel(const int* __restrict__ ei, int E) {
    int e = blockIdx.x * blockDim.x + threadIdx.x;
    if (e < E) atomicAdd(&g_deg[ei[E + e]], 1.0f);
}

// ---------------------------------------------------------------------------
// 3) GEMM: h[n][o] = sum_k x[n][k] * W[o][k]
//    4 threads per node, 16 outputs each (8 f32x2 accumulators, ~40 regs ->
//    ~4x higher occupancy than the 2-node/32-output tile).
//    Epilogue: dinv[n] = rsqrt(deg[n]) (fused),
//              out[n][o] = h[n][o]*dinv[n]^2 + b[o]  (self-loop + bias,
//              fully initializes the poisoned output buffer).
// ---------------------------------------------------------------------------
__global__ __launch_bounds__(256)
void gemm_kernel(const float* __restrict__ x,
                 const float* __restrict__ W,
                 const float* __restrict__ bias,
                 float* __restrict__ out, int N) {
    __shared__ float Ws[D * D];   // Ws[k*64 + o] = W[o][k]  (transposed)
    for (int t = threadIdx.x; t < D * D; t += 256) {
        int o = t >> 6;
        int k = t & 63;
        Ws[k * D + o] = W[t];
    }
    __syncthreads();

    int t = blockIdx.x * 256 + threadIdx.x;
    if (t >= N * 4) return;
    int n = t >> 2;
    int q = t & 3;                 // output quarter: cols [16q, 16q+16)

    unsigned long long acc[8];
#pragma unroll
    for (int m = 0; m < 8; m++) acc[m] = 0ULL;

    const float4* xr = (const float4*)(x + (size_t)n * D);

#pragma unroll 1
    for (int i4 = 0; i4 < 16; i4++) {
        float4 xv = xr[i4];        // 4 adjacent threads load the same row -> L1 hit
        float xs[4] = {xv.x, xv.y, xv.z, xv.w};
#pragma unroll
        for (int kk = 0; kk < 4; kk++) {
            int k = i4 * 4 + kk;
            unsigned long long xx;
            asm("mov.b64 %0, {%1, %1};" : "=l"(xx) : "f"(xs[kk]));
            const ulonglong2* wp = (const ulonglong2*)(Ws + k * D + q * 16);
            ulonglong2 w0 = wp[0], w1 = wp[1], w2 = wp[2], w3 = wp[3];
            asm("fma.rn.f32x2 %0, %1, %2, %0;" : "+l"(acc[0]) : "l"(xx), "l"(w0.x));
            asm("fma.rn.f32x2 %0, %1, %2, %0;" : "+l"(acc[1]) : "l"(xx), "l"(w0.y));
            asm("fma.rn.f32x2 %0, %1, %2, %0;" : "+l"(acc[2]) : "l"(xx), "l"(w1.x));
            asm("fma.rn.f32x2 %0, %1, %2, %0;" : "+l"(acc[3]) : "l"(xx), "l"(w1.y));
            asm("fma.rn.f32x2 %0, %1, %2, %0;" : "+l"(acc[4]) : "l"(xx), "l"(w2.x));
            asm("fma.rn.f32x2 %0, %1, %2, %0;" : "+l"(acc[5]) : "l"(xx), "l"(w2.y));
            asm("fma.rn.f32x2 %0, %1, %2, %0;" : "+l"(acc[6]) : "l"(xx), "l"(w3.x));
            asm("fma.rn.f32x2 %0, %1, %2, %0;" : "+l"(acc[7]) : "l"(xx), "l"(w3.y));
        }
    }

    float dv = rsqrtf(g_deg[n]);   // broadcast load across the 4 node-threads
    if (q == 0) g_dinv[n] = dv;
    float sl = dv * dv;

    float* hrow = g_h + (size_t)n * D + q * 16;
    float* orow = out + (size_t)n * D + q * 16;
    const float4* brow = (const float4*)(bias + q * 16);
#pragma unroll
    for (int m = 0; m < 4; m++) {
        float f0, f1, f2, f3;
        asm("mov.b64 {%0, %1}, %2;" : "=f"(f0), "=f"(f1) : "l"(acc[2 * m]));
        asm("mov.b64 {%0, %1}, %2;" : "=f"(f2), "=f"(f3) : "l"(acc[2 * m + 1]));
        ((float4*)hrow)[m] = make_float4(f0, f1, f2, f3);
        float4 bb = __ldg(&brow[m]);
        float4 ov;
        ov.x = fmaf(f0, sl, bb.x);
        ov.y = fmaf(f1, sl, bb.y);
        ov.z = fmaf(f2, sl, bb.z);
        ov.w = fmaf(f3, sl, bb.w);
        ((float4*)orow)[m] = ov;
    }
}

// ---------------------------------------------------------------------------
// 4) Edge scatter: out[dst] += h[src] * (dinv[src]*dinv[dst])
//    16 threads per edge, one float4 per thread, vector red.
// ---------------------------------------------------------------------------
__global__ __launch_bounds__(256)
void scatter_kernel(const int* __restrict__ ei,
                    float* __restrict__ out, int E) {
    long long gid = (long long)blockIdx.x * blockDim.x + threadIdx.x;
    int e = (int)(gid >> 4);
    int l = (int)(gid & 15);
    if (e >= E) return;

    int s = __ldg(&ei[e]);        // src
    int d = __ldg(&ei[E + e]);    // dst
    float norm = g_dinv[s] * g_dinv[d];

    float4 v = ((const float4*)g_h)[(size_t)s * 16 + l];
    v.x *= norm; v.y *= norm; v.z *= norm; v.w *= norm;

    float* o = out + ((size_t)d * D + l * 4);
    asm volatile("red.global.add.v4.f32 [%0], {%1, %2, %3, %4};"
                 :: "l"(o), "f"(v.x), "f"(v.y), "f"(v.z), "f"(v.w)
                 : "memory");
}

// ---------------------------------------------------------------------------
extern "C" void kernel_launch(void* const* d_in, const int* in_sizes, int n_in,
                              void* d_out, int out_size) {
    const float* x  = (const float*)d_in[0];
    const int*   ei = (const int*)d_in[1];
    const float* W  = (const float*)d_in[2];
    const float* b  = (const float*)d_in[3];
    float*       out = (float*)d_out;

    int N = in_sizes[0] / D;   // 100000
    int E = in_sizes[1] / 2;   // 1000000

    int N4 = N / 4;            // N divisible by 4
    deg_init_kernel<<<(N4 + 255) / 256, 256>>>(N4);
    deg_acc_kernel<<<(E + 255) / 256, 256>>>(ei, E);
    gemm_kernel<<<(N * 4 + 255) / 256, 256>>>(x, W, b, out, N);

    long long total = (long long)E * 16;
    int nb_s = (int)((total + 255) / 256);
    scatter_kernel<<<nb_s, 256>>>(ei, out, E);
}

// round 6
// speedup vs baseline: 1.3527x; 1.3459x over previous
#include <cuda_runtime.h>

#define MAX_N 100000
#define MAX_E 1000000
#define D 64

// Scratch (device globals: sanctioned alternative to cudaMalloc)
__device__ float g_h[MAX_N * D];     // h = x @ W^T
__device__ float g_dinv[MAX_N];
__device__ int   g_cnt[MAX_N];       // in-degree (excl. self-loop)
__device__ int   g_start[MAX_N];     // CSR row starts (exclusive scan of cnt)
__device__ int   g_cursor[MAX_N];    // fill cursors
__device__ int   g_ebuf[MAX_E];      // src node per edge, bucketed by dst
__device__ int   g_bsum[128];        // scan block sums

// ---------------------------------------------------------------------------
// 1) zero the degree histogram
// ---------------------------------------------------------------------------
__global__ void zero_cnt_kernel(int N) {
    int i = blockIdx.x * blockDim.x + threadIdx.x;
    if (i < N) g_cnt[i] = 0;
}

// 2) histogram in-degree over edge dst (edge_index is int32)
__global__ void deg_acc_kernel(const int* __restrict__ ei, int E) {
    int e = blockIdx.x * blockDim.x + threadIdx.x;
    if (e < E) atomicAdd(&g_cnt[ei[E + e]], 1);
}

// ---------------------------------------------------------------------------
// 3) two-level exclusive scan of g_cnt -> g_start; scan3 also emits dinv
// ---------------------------------------------------------------------------
__global__ __launch_bounds__(1024)
void scan1_kernel(int N) {
    __shared__ int wsum[32];
    int i = blockIdx.x * 1024 + threadIdx.x;
    int lane = threadIdx.x & 31;
    int wid  = threadIdx.x >> 5;
    int v = (i < N) ? g_cnt[i] : 0;
    int val = v;
#pragma unroll
    for (int off = 1; off < 32; off <<= 1) {
        int t = __shfl_up_sync(0xffffffffu, val, off);
        if (lane >= off) val += t;
    }
    if (lane == 31) wsum[wid] = val;
    __syncthreads();
    if (wid == 0) {
        int w = wsum[lane];
#pragma unroll
        for (int off = 1; off < 32; off <<= 1) {
            int t = __shfl_up_sync(0xffffffffu, w, off);
            if (lane >= off) w += t;
        }
        wsum[lane] = w;
    }
    __syncthreads();
    int incl = val + (wid > 0 ? wsum[wid - 1] : 0);
    if (i < N) g_start[i] = incl - v;
    if (threadIdx.x == 1023) g_bsum[blockIdx.x] = incl;
}

__global__ __launch_bounds__(128)
void scan2_kernel(int nb) {
    __shared__ int wsum[4];
    int lane = threadIdx.x & 31;
    int wid  = threadIdx.x >> 5;
    int v = (threadIdx.x < nb) ? g_bsum[threadIdx.x] : 0;
    int val = v;
#pragma unroll
    for (int off = 1; off < 32; off <<= 1) {
        int t = __shfl_up_sync(0xffffffffu, val, off);
        if (lane >= off) val += t;
    }
    if (lane == 31) wsum[wid] = val;
    __syncthreads();
    int pre = 0;
    for (int w = 0; w < wid; w++) pre += wsum[w];
    if (threadIdx.x < nb) g_bsum[threadIdx.x] = val - v + pre;  // exclusive
}

__global__ void scan3_kernel(int N) {
    int i = blockIdx.x * blockDim.x + threadIdx.x;
    if (i < N) {
        int s = g_start[i] + g_bsum[i >> 10];
        g_start[i]  = s;
        g_cursor[i] = s;
        g_dinv[i]   = rsqrtf(1.0f + (float)g_cnt[i]);   // self-loop included
    }
}

// 4) bucket fill: edges grouped by dst, payload = src
__global__ void fill_kernel(const int* __restrict__ ei, int E) {
    int e = blockIdx.x * blockDim.x + threadIdx.x;
    if (e < E) {
        int s = ei[e];
        int d = ei[E + e];
        int pos = atomicAdd(&g_cursor[d], 1);
        g_ebuf[pos] = s;
    }
}

// ---------------------------------------------------------------------------
// 5) GEMM: h[n][o] = sum_k x[n][k] * W[o][k]
//    Warp-uniform tiling: warp = (node-group, output-quarter q). All 32 lanes
//    share q -> W smem loads are pure broadcast LDS.128 (conflict-free).
//    Lane owns 1 node x 16 outputs in 8 f32x2 accumulators (~50 regs).
// ---------------------------------------------------------------------------
__global__ __launch_bounds__(256)
void gemm_kernel(const float* __restrict__ x,
                 const float* __restrict__ W, int N) {
    __shared__ float Ws[D * D];   // Ws[k*64 + o] = W[o][k]  (transposed)
    for (int t = threadIdx.x; t < D * D; t += 256) {
        int o = t >> 6;
        int k = t & 63;
        Ws[k * D + o] = W[t];
    }
    __syncthreads();

    int w    = threadIdx.x >> 5;          // warp 0..7
    int lane = threadIdx.x & 31;
    int q    = w & 3;                     // output quarter (warp-uniform!)
    int n    = blockIdx.x * 64 + (w >> 2) * 32 + lane;
    if (n >= N) return;

    unsigned long long acc[8];
#pragma unroll
    for (int m = 0; m < 8; m++) acc[m] = 0ULL;

    const float4* xr = (const float4*)(x + (size_t)n * D);

#pragma unroll 1
    for (int i4 = 0; i4 < 16; i4++) {
        float4 xv = xr[i4];
        float xs[4] = {xv.x, xv.y, xv.z, xv.w};
#pragma unroll
        for (int kk = 0; kk < 4; kk++) {
            int k = i4 * 4 + kk;
            unsigned long long xx;
            asm("mov.b64 %0, {%1, %1};" : "=l"(xx) : "f"(xs[kk]));
            const ulonglong2* wp = (const ulonglong2*)(Ws + k * D + q * 16);
            ulonglong2 w0 = wp[0], w1 = wp[1], w2 = wp[2], w3 = wp[3];
            asm("fma.rn.f32x2 %0, %1, %2, %0;" : "+l"(acc[0]) : "l"(xx), "l"(w0.x));
            asm("fma.rn.f32x2 %0, %1, %2, %0;" : "+l"(acc[1]) : "l"(xx), "l"(w0.y));
            asm("fma.rn.f32x2 %0, %1, %2, %0;" : "+l"(acc[2]) : "l"(xx), "l"(w1.x));
            asm("fma.rn.f32x2 %0, %1, %2, %0;" : "+l"(acc[3]) : "l"(xx), "l"(w1.y));
            asm("fma.rn.f32x2 %0, %1, %2, %0;" : "+l"(acc[4]) : "l"(xx), "l"(w2.x));
            asm("fma.rn.f32x2 %0, %1, %2, %0;" : "+l"(acc[5]) : "l"(xx), "l"(w2.y));
            asm("fma.rn.f32x2 %0, %1, %2, %0;" : "+l"(acc[6]) : "l"(xx), "l"(w3.x));
            asm("fma.rn.f32x2 %0, %1, %2, %0;" : "+l"(acc[7]) : "l"(xx), "l"(w3.y));
        }
    }

    float* hrow = g_h + (size_t)n * D + q * 16;
#pragma unroll
    for (int m = 0; m < 4; m++) {
        float f0, f1, f2, f3;
        asm("mov.b64 {%0, %1}, %2;" : "=f"(f0), "=f"(f1) : "l"(acc[2 * m]));
        asm("mov.b64 {%0, %1}, %2;" : "=f"(f2), "=f"(f3) : "l"(acc[2 * m + 1]));
        ((float4*)hrow)[m] = make_float4(f0, f1, f2, f3);
    }
}

// ---------------------------------------------------------------------------
// 6) Gather: one warp per node, 4-deep unrolled for MLP.
//    out[n] = b + dinv[n]^2 * h[n] + dinv[n] * sum_{s in in(n)} dinv[s]*h[s]
//    No atomics; out written exactly once (covers the poisoned buffer).
// ---------------------------------------------------------------------------
__global__ __launch_bounds__(256)
void gather_kernel(const float* __restrict__ bias,
                   float* __restrict__ out, int N) {
    int warp = (blockIdx.x * 256 + threadIdx.x) >> 5;
    int lane = threadIdx.x & 31;
    if (warp >= N) return;
    int n = warp;

    int start = g_start[n];
    int cnt   = g_cnt[n];

    float2 a0 = make_float2(0.f, 0.f);
    float2 a1 = make_float2(0.f, 0.f);
    float2 a2 = make_float2(0.f, 0.f);
    float2 a3 = make_float2(0.f, 0.f);

    int i = 0;
    for (; i + 4 <= cnt; i += 4) {
        int s0 = __ldg(&g_ebuf[start + i]);
        int s1 = __ldg(&g_ebuf[start + i + 1]);
        int s2 = __ldg(&g_ebuf[start + i + 2]);
        int s3 = __ldg(&g_ebuf[start + i + 3]);
        float d0 = __ldg(&g_dinv[s0]);
        float d1 = __ldg(&g_dinv[s1]);
        float d2 = __ldg(&g_dinv[s2]);
        float d3 = __ldg(&g_dinv[s3]);
        float2 v0 = ((const float2*)g_h)[(size_t)s0 * 32 + lane];
        float2 v1 = ((const float2*)g_h)[(size_t)s1 * 32 + lane];
        float2 v2 = ((const float2*)g_h)[(size_t)s2 * 32 + lane];
        float2 v3 = ((const float2*)g_h)[(size_t)s3 * 32 + lane];
        a0.x = fmaf(d0, v0.x, a0.x);  a0.y = fmaf(d0, v0.y, a0.y);
        a1.x = fmaf(d1, v1.x, a1.x);  a1.y = fmaf(d1, v1.y, a1.y);
        a2.x = fmaf(d2, v2.x, a2.x);  a2.y = fmaf(d2, v2.y, a2.y);
        a3.x = fmaf(d3, v3.x, a3.x);  a3.y = fmaf(d3, v3.y, a3.y);
    }
    for (; i < cnt; i++) {
        int s0 = __ldg(&g_ebuf[start + i]);
        float d0 = __ldg(&g_dinv[s0]);
        float2 v0 = ((const float2*)g_h)[(size_t)s0 * 32 + lane];
        a0.x = fmaf(d0, v0.x, a0.x);  a0.y = fmaf(d0, v0.y, a0.y);
    }
    a0.x += a1.x + a2.x + a3.x;
    a0.y += a1.y + a2.y + a3.y;

    float dn  = g_dinv[n];
    float sl  = dn * dn;
    float2 hn = ((const float2*)g_h)[(size_t)n * 32 + lane];
    float2 bb = ((const float2*)bias)[lane];
    float2 o;
    o.x = bb.x + sl * hn.x + dn * a0.x;
    o.y = bb.y + sl * hn.y + dn * a0.y;
    ((float2*)out)[(size_t)n * 32 + lane] = o;
}

// ---------------------------------------------------------------------------
extern "C" void kernel_launch(void* const* d_in, const int* in_sizes, int n_in,
                              void* d_out, int out_size) {
    const float* x  = (const float*)d_in[0];
    const int*   ei = (const int*)d_in[1];
    const float* W  = (const float*)d_in[2];
    const float* b  = (const float*)d_in[3];
    float*       out = (float*)d_out;

    int N = in_sizes[0] / D;   // 100000
    int E = in_sizes[1] / 2;   // 1000000
    int nb = (N + 1023) / 1024;

    zero_cnt_kernel<<<(N + 255) / 256, 256>>>(N);
    deg_acc_kernel<<<(E + 255) / 256, 256>>>(ei, E);
    scan1_kernel<<<nb, 1024>>>(N);
    scan2_kernel<<<1, 128>>>(nb);
    scan3_kernel<<<(N + 255) / 256, 256>>>(N);
    fill_kernel<<<(E + 255) / 256, 256>>>(ei, E);
    gemm_kernel<<<(N + 63) / 64, 256>>>(x, W, N);
    gather_kernel<<<(N * 32 + 255) / 256, 256>>>(b, out, N);
}